// round 14
// baseline (speedup 1.0000x reference)
#include <cuda_runtime.h>
#include <math.h>

#define NTHREADS 256
#define MAXB 8192

__device__ float g_nfv[MAXB * 64];

typedef unsigned long long u64;

// ---- f32x2 packed helpers (sm_100+) ----
__device__ __forceinline__ u64 pk2(float a, float b) {
    u64 r; asm("mov.b64 %0, {%1,%2};" : "=l"(r) : "f"(a), "f"(b)); return r;
}
__device__ __forceinline__ float2 upk2(u64 v) {
    float2 r; asm("mov.b64 {%0,%1}, %2;" : "=f"(r.x), "=f"(r.y) : "l"(v)); return r;
}
__device__ __forceinline__ u64 fma2(u64 a, u64 b, u64 c) {
    u64 d; asm("fma.rn.f32x2 %0, %1, %2, %3;" : "=l"(d) : "l"(a), "l"(b), "l"(c)); return d;
}
__device__ __forceinline__ u64 mul2(u64 a, u64 b) {
    u64 d; asm("mul.rn.f32x2 %0, %1, %2;" : "=l"(d) : "l"(a), "l"(b)); return d;
}
__device__ __forceinline__ u64 add2(u64 a, u64 b) {
    u64 d; asm("add.rn.f32x2 %0, %1, %2;" : "=l"(d) : "l"(a), "l"(b)); return d;
}
__device__ __forceinline__ u64 abs2(u64 a) {
    u64 d; asm("and.b64 %0, %1, %2;" : "=l"(d) : "l"(a), "l"(0x7FFFFFFF7FFFFFFFULL)); return d;
}

__device__ __forceinline__ float red8(float p) {
    p += __shfl_xor_sync(0xffffffffu, p, 1);
    p += __shfl_xor_sync(0xffffffffu, p, 2);
    p += __shfl_xor_sync(0xffffffffu, p, 4);
    return p;
}
__device__ __forceinline__ float hsum(u64 t) { float2 v = upk2(t); return v.x + v.y; }

__device__ __forceinline__ float dot8p(ulonglong2 A0, ulonglong2 A1,
                                       u64 r0, u64 r1, u64 r2, u64 r3) {
    u64 t = mul2(A0.x, r0);
    t = fma2(A0.y, r1, t);
    t = fma2(A1.x, r2, t);
    t = fma2(A1.y, r3, t);
    return hsum(t);
}
__device__ __forceinline__ float absdot8p(ulonglong2 A0, ulonglong2 A1,
                                          ulonglong2 G0, ulonglong2 G1,
                                          u64 r0, u64 r1, u64 r2, u64 r3) {
    u64 t = mul2(A0.x, abs2(add2(G0.x, r0)));
    t = fma2(A0.y, abs2(add2(G0.y, r1)), t);
    t = fma2(A1.x, abs2(add2(G1.x, r2)), t);
    t = fma2(A1.y, abs2(add2(G1.y, r3)), t);
    return hsum(t);
}

// smem layout (floats) — 9408 floats = 37,632 B; smem/SM=188KB @occ5 -> L1D=40KB
#define OFF_ATT1 0      // 256
#define OFF_B1   256    // 256
#define OFF_ATT2 512    // 64
#define OFF_B2   576    // 64
#define OFF_X    640    // 168
#define OFF_AJ   808    // 88   (A2 / colsum reuse this after layer 1)
#define OFF_GL1  896    // 5376 (21x256) -> h1 after step E
#define OFF_SCR  6272   // 3136 scratch
#define SMEM_FLOATS 9408
// scratch life: e1 [i*84+j*4+h] (1764) -> alphaT [h*504+j*24+i] (2016, after D barrier)
//            -> gl2 @0 (1344), gr2 @1344 (1344), e2 @2688 (441).

__global__ __launch_bounds__(NTHREADS, 5) void actor_kernel(
    const float* __restrict__ state24,
    const float* __restrict__ Wl1, const float* __restrict__ Wr1,
    const float* __restrict__ att1, const float* __restrict__ b1,
    const float* __restrict__ Wl2, const float* __restrict__ Wr2,
    const float* __restrict__ att2, const float* __restrict__ b2)
{
    extern __shared__ float sm[];
    float* sAtt1 = sm + OFF_ATT1;
    float* sB1   = sm + OFF_B1;
    float* sAtt2 = sm + OFF_ATT2;
    float* sB2   = sm + OFF_B2;
    float* sX    = sm + OFF_X;
    float* sAj   = sm + OFF_AJ;
    float* sGL1  = sm + OFF_GL1;
    float* sSCR  = sm + OFF_SCR;

    const int tid  = threadIdx.x;
    const int lane = tid & 31;
    const int warp = tid >> 5;
    const int b    = blockIdx.x;
    const float* st = state24 + b * 24;

    const int g = lane >> 3, q = lane & 7;
    const int off0 = g * 64 + q * 4;
    const int off1 = off0 + 32;
    const int offq0 = q * 4;
    const int offq1 = q * 4 + 32;

    sAtt1[tid] = att1[tid];
    sB1[tid]   = b1[tid];
    if (tid < 64) { sAtt2[tid] = att2[tid]; sB2[tid] = b2[tid]; }

    if (tid < 21) {
        float f0, f1, f2, f3, f4, f5, f6;
        if (tid < 20) {
            double ang = (-1.6007963267948966 + 0.15707963267948966)
                       + (double)tid * 0.15857963267948968;
            float a = (float)ang;
            f0 = st[tid] * 0.1f;
            f1 = sinf(a); f2 = cosf(a);
            f3 = f4 = f5 = f6 = 0.f;
        } else {
            f0 = f1 = f2 = 0.f;
            f3 = st[20]; f4 = st[21]; f5 = st[22]; f6 = st[23];
        }
        float* xr = sX + tid * 8;
        xr[0]=f0; xr[1]=f1; xr[2]=f2; xr[3]=f3; xr[4]=f4; xr[5]=f5; xr[6]=f6; xr[7]=0.f;
    }
    __syncthreads();

    // ---- B: gl1 = x @ Wl1 ----
    {
        const int c = tid;
        float wl[7];
        #pragma unroll
        for (int k = 0; k < 7; k++) wl[k] = Wl1[k*256 + c];
        #pragma unroll 3
        for (int i = 0; i < 21; i++) {
            const float* xr = sX + i*8;
            float a = 0.f;
            #pragma unroll
            for (int k = 0; k < 7; k++) a = fmaf(xr[k], wl[k], a);
            sGL1[i*256 + c] = a;
        }
    }
    __syncthreads();

    const ulonglong2 A0 = *(const ulonglong2*)&sAtt1[off0];
    const ulonglong2 A1 = *(const ulonglong2*)&sAtt1[off1];

    // ---- Aj ----
    for (int j = warp; j < 21; j += 8) {
        ulonglong2 G0 = *(const ulonglong2*)&sGL1[j*256 + off0];
        ulonglong2 G1 = *(const ulonglong2*)&sGL1[j*256 + off1];
        float p = red8(dot8p(A0, A1, G0.x, G0.y, G1.x, G1.y));
        if (q == 0) sAj[j*4 + g] = p;
    }
    __syncthreads();

    // ---- C: e1[i,j,h] = 0.6(A_j + B_i) + 0.4 * sum_d att|gl_j + gr_i| ----
    {
        float* sE1 = sSCR;
        {
            const int i0 = warp, i1 = warp + 8;
            u64 ra[4] = {0,0,0,0}, rb[4] = {0,0,0,0};
            #pragma unroll
            for (int m = 0; m < 7; m++) {
                ulonglong2 w0 = *(const ulonglong2*)&Wr1[m*256 + off0];
                ulonglong2 w1 = *(const ulonglong2*)&Wr1[m*256 + off1];
                float xav = sX[i0*8 + m], xbv = sX[i1*8 + m];
                u64 xa = pk2(xav, xav), xb = pk2(xbv, xbv);
                ra[0] = fma2(xa, w0.x, ra[0]); ra[1] = fma2(xa, w0.y, ra[1]);
                ra[2] = fma2(xa, w1.x, ra[2]); ra[3] = fma2(xa, w1.y, ra[3]);
                rb[0] = fma2(xb, w0.x, rb[0]); rb[1] = fma2(xb, w0.y, rb[1]);
                rb[2] = fma2(xb, w1.x, rb[2]); rb[3] = fma2(xb, w1.y, rb[3]);
            }
            float Bp0 = red8(dot8p(A0, A1, ra[0], ra[1], ra[2], ra[3]));
            float Bp1 = red8(dot8p(A0, A1, rb[0], rb[1], rb[2], rb[3]));
            #pragma unroll 3
            for (int j = 0; j < 21; j++) {
                ulonglong2 G0 = *(const ulonglong2*)&sGL1[j*256 + off0];
                ulonglong2 G1 = *(const ulonglong2*)&sGL1[j*256 + off1];
                float t0 = absdot8p(A0, A1, G0, G1, ra[0], ra[1], ra[2], ra[3]);
                float t1 = absdot8p(A0, A1, G0, G1, rb[0], rb[1], rb[2], rb[3]);
                t0 = red8(t0);
                t1 = red8(t1);
                if (q == 0) {
                    float ajv = sAj[j*4 + g];
                    sE1[(i0*21 + j)*4 + g] = fmaf(0.4f, t0, 0.6f * (ajv + Bp0));
                    sE1[(i1*21 + j)*4 + g] = fmaf(0.4f, t1, 0.6f * (ajv + Bp1));
                }
            }
        }
        if (warp < 5) {
            const int i2 = warp + 16;
            u64 rr[4] = {0,0,0,0};
            #pragma unroll
            for (int m = 0; m < 7; m++) {
                ulonglong2 w0 = *(const ulonglong2*)&Wr1[m*256 + off0];
                ulonglong2 w1 = *(const ulonglong2*)&Wr1[m*256 + off1];
                float xv = sX[i2*8 + m];
                u64 xp = pk2(xv, xv);
                rr[0] = fma2(xp, w0.x, rr[0]); rr[1] = fma2(xp, w0.y, rr[1]);
                rr[2] = fma2(xp, w1.x, rr[2]); rr[3] = fma2(xp, w1.y, rr[3]);
            }
            float Bp = red8(dot8p(A0, A1, rr[0], rr[1], rr[2], rr[3]));
            #pragma unroll 3
            for (int j = 0; j < 21; j++) {
                ulonglong2 G0 = *(const ulonglong2*)&sGL1[j*256 + off0];
                ulonglong2 G1 = *(const ulonglong2*)&sGL1[j*256 + off1];
                float t = red8(absdot8p(A0, A1, G0, G1, rr[0], rr[1], rr[2], rr[3]));
                if (q == 0)
                    sE1[(i2*21 + j)*4 + g] = fmaf(0.4f, t, 0.6f * (sAj[j*4 + g] + Bp));
            }
        }
    }
    __syncthreads();

    // ---- D: softmax over j (e1 -> regs), barrier, write alphaT over e1 ----
    {
        float v[21];
        const int i = tid >> 2, h = tid & 3;
        if (tid < 84) {
            const float* row = sSCR + i*84 + h;
            float m = -1e30f;
            #pragma unroll
            for (int j = 0; j < 21; j++) { v[j] = row[j*4]; m = fmaxf(m, v[j]); }
            float s = 0.f;
            #pragma unroll
            for (int j = 0; j < 21; j++) { v[j] = __expf(v[j] - m); s += v[j]; }
            float inv = 1.f / s;
            #pragma unroll
            for (int j = 0; j < 21; j++) v[j] *= inv;
        }
        __syncthreads();
        if (tid < 84) {
            float* at = sSCR + h*504 + i;
            #pragma unroll
            for (int j = 0; j < 21; j++) at[j*24] = v[j];
        }
    }
    __syncthreads();

    // ---- E: h1 = elu(alpha1 @ gl1 + b1) -> overwrite sGL1 ----
    {
        const int c = tid, h = c >> 6;
        u64 acc[10];
        #pragma unroll
        for (int p = 0; p < 10; p++) acc[p] = 0ULL;
        float acc20 = 0.f;
        const float* aT = sSCR + h*504;
        #pragma unroll 3
        for (int j = 0; j < 21; j++) {
            float gv = sGL1[j*256 + c];
            u64 gg = pk2(gv, gv);
            const ulonglong2* ap = (const ulonglong2*)(aT + j*24);
            ulonglong2 p0 = ap[0];
            acc[0] = fma2(p0.x, gg, acc[0]); acc[1] = fma2(p0.y, gg, acc[1]);
            ulonglong2 p1 = ap[1];
            acc[2] = fma2(p1.x, gg, acc[2]); acc[3] = fma2(p1.y, gg, acc[3]);
            ulonglong2 p2 = ap[2];
            acc[4] = fma2(p2.x, gg, acc[4]); acc[5] = fma2(p2.y, gg, acc[5]);
            ulonglong2 p3 = ap[3];
            acc[6] = fma2(p3.x, gg, acc[6]); acc[7] = fma2(p3.y, gg, acc[7]);
            ulonglong2 p4 = ap[4];
            acc[8] = fma2(p4.x, gg, acc[8]); acc[9] = fma2(p4.y, gg, acc[9]);
            acc20 = fmaf(aT[j*24 + 20], gv, acc20);
        }
        float bc = sB1[c];
        #pragma unroll
        for (int p = 0; p < 10; p++) {
            float2 v = upk2(acc[p]);
            float v0 = v.x + bc;
            float v1 = v.y + bc;
            v0 = fmaxf(v0, 0.f) + __expf(fminf(v0, 0.f)) - 1.f;
            v1 = fmaxf(v1, 0.f) + __expf(fminf(v1, 0.f)) - 1.f;
            sGL1[(2*p  )*256 + c] = v0;
            sGL1[(2*p+1)*256 + c] = v1;
        }
        float v20 = acc20 + bc;
        v20 = fmaxf(v20, 0.f) + __expf(fminf(v20, 0.f)) - 1.f;
        sGL1[20*256 + c] = v20;
    }
    __syncthreads();

    // ---- F: gl2 / gr2 = h1 @ Wl2 / Wr2 ----
    {
        const int d    = tid & 63;
        const int sel  = (tid >> 6) & 1;
        const int half = tid >> 7;
        const float* __restrict__ W = sel ? Wr2 : Wl2;
        float* G = sSCR + (sel ? 1344 : 0);
        const int i0 = half ? 11 : 0;
        u64 acc[11];
        #pragma unroll
        for (int i = 0; i < 11; i++) acc[i] = 0ULL;
        for (int k = 0; k < 256; k += 4) {
            float w0 = W[(k+0)*64 + d];
            float w1 = W[(k+1)*64 + d];
            float w2 = W[(k+2)*64 + d];
            float w3 = W[(k+3)*64 + d];
            u64 wp01 = pk2(w0, w1);
            u64 wp23 = pk2(w2, w3);
            #pragma unroll
            for (int i = 0; i < 11; i++) {
                if (i0 + i < 21) {
                    ulonglong2 h2 = *(const ulonglong2*)&sGL1[(i0+i)*256 + k];
                    acc[i] = fma2(wp01, h2.x, acc[i]);
                    acc[i] = fma2(wp23, h2.y, acc[i]);
                }
            }
        }
        #pragma unroll
        for (int i = 0; i < 11; i++) {
            if (i0 + i < 21) {
                float2 s = upk2(acc[i]);
                G[(i0+i)*64 + d] = s.x + s.y;
            }
        }
    }
    __syncthreads();

    const ulonglong2 A0q = *(const ulonglong2*)&sAtt2[offq0];
    const ulonglong2 A1q = *(const ulonglong2*)&sAtt2[offq1];

    // ---- A2 (stored in the dead Aj slot) ----
    {
        const float* gl2 = sSCR;
        float* sA2 = sAj;
        int j = warp + 8*g;
        int jc = (j < 21) ? j : 20;
        ulonglong2 G0 = *(const ulonglong2*)&gl2[jc*64 + offq0];
        ulonglong2 G1 = *(const ulonglong2*)&gl2[jc*64 + offq1];
        float p = red8(dot8p(A0q, A1q, G0.x, G0.y, G1.x, G1.y));
        if (q == 0 && j < 21) sA2[j] = p;
    }
    __syncthreads();

    // ---- C2 ----
    {
        const float* gl2 = sSCR;
        const float* gr2 = sSCR + 1344;
        const float* sA2 = sAj;
        float* sE2 = sSCR + 2688;
        for (int i = warp; i < 21; i += 8) {
            ulonglong2 R0 = *(const ulonglong2*)&gr2[i*64 + offq0];
            ulonglong2 R1 = *(const ulonglong2*)&gr2[i*64 + offq1];
            float Bp = red8(dot8p(A0q, A1q, R0.x, R0.y, R1.x, R1.y));
            #pragma unroll
            for (int jb = 0; jb < 21; jb += 4) {
                int j = jb + g;
                int jc = (j < 21) ? j : 20;
                ulonglong2 G0 = *(const ulonglong2*)&gl2[jc*64 + offq0];
                ulonglong2 G1 = *(const ulonglong2*)&gl2[jc*64 + offq1];
                float t = red8(absdot8p(A0q, A1q, G0, G1, R0.x, R0.y, R1.x, R1.y));
                if (q == 0 && j < 21)
                    sE2[i*21 + j] = fmaf(0.4f, t, 0.6f * (sA2[j] + Bp));
            }
        }
    }
    __syncthreads();

    // ---- softmax2: 8-lane group per row; ALL lanes run ALL shfls (clamped idx) ----
    {
        float* sE2 = sSCR + 2688;
        const int i  = warp*4 + g;
        const int ic = (i < 21) ? i : 20;
        float* row = sE2 + ic*21;
        float v0 = row[q];
        float v1 = row[q + 8];
        float v2 = (q < 5) ? row[q + 16] : -1e30f;
        float m = fmaxf(fmaxf(v0, v1), v2);
        m = fmaxf(m, __shfl_xor_sync(0xffffffffu, m, 1));
        m = fmaxf(m, __shfl_xor_sync(0xffffffffu, m, 2));
        m = fmaxf(m, __shfl_xor_sync(0xffffffffu, m, 4));
        v0 = __expf(v0 - m);
        v1 = __expf(v1 - m);
        v2 = (q < 5) ? __expf(v2 - m) : 0.f;
        float s = v0 + v1 + v2;
        s += __shfl_xor_sync(0xffffffffu, s, 1);
        s += __shfl_xor_sync(0xffffffffu, s, 2);
        s += __shfl_xor_sync(0xffffffffu, s, 4);
        float inv = 1.f / s;
        if (i < 21) {
            row[q]     = v0 * inv;
            row[q + 8] = v1 * inv;
            if (q < 5) row[q + 16] = v2 * inv;
        }
    }
    __syncthreads();

    // ---- colsum: w[j] = (1/21) sum_i alpha2[i,j]  (E2+pool collapsed) ----
    if (tid < 21) {
        const float* al = sSCR + 2688;
        float s = 0.f;
        #pragma unroll 7
        for (int i = 0; i < 21; i++) s += al[i*21 + tid];
        sAj[tid] = s * (1.0f / 21.0f);     // overwrite dead A2
    }
    __syncthreads();

    // ---- nfv[d] = sum_j w[j] * gl2[j,d] + b2[d] -> global ----
    if (tid < 64) {
        const float* gl2 = sSCR;
        float acc = 0.f;
        #pragma unroll 7
        for (int j = 0; j < 21; j++) acc = fmaf(sAj[j], gl2[j*64 + tid], acc);
        g_nfv[b*64 + tid] = acc + sB2[tid];
    }
}

// ====== FC head kernel: 6 rows/block (grid 171 >= 148 SMs), deep LDG batching ======
#define FC_ROWS 6

__global__ __launch_bounds__(256, 2) void fc_kernel(
    const float* __restrict__ fc1w, const float* __restrict__ fc1b,
    const float* __restrict__ fc2w, const float* __restrict__ fc2b,
    const float* __restrict__ fc3w, const float* __restrict__ fc3b,
    float* __restrict__ out, int B)
{
    __shared__ float sN [FC_ROWS * 64];
    __shared__ float sF1[FC_ROWS * 256];
    __shared__ float sF2[FC_ROWS * 256];
    const int tid = threadIdx.x;
    const int r0  = blockIdx.x * FC_ROWS;

    if (tid < FC_ROWS * 16) {
        int rr = r0 + (tid >> 4);
        int rc = (rr < B) ? rr : (B - 1);
        ((float4*)sN)[tid] = *(const float4*)&g_nfv[rc*64 + (tid & 15)*4];
    }
    __syncthreads();

    // fc1: 64 -> 256, 8-pair (16 LDG) batches
    {
        const int c = tid;
        u64 acc[FC_ROWS];
        #pragma unroll
        for (int r = 0; r < FC_ROWS; r++) acc[r] = 0ULL;
        #pragma unroll
        for (int kb = 0; kb < 32; kb += 8) {
            u64 wp[8];
            #pragma unroll
            for (int t = 0; t < 8; t++)
                wp[t] = pk2(fc1w[(2*(kb+t))*256 + c], fc1w[(2*(kb+t)+1)*256 + c]);
            #pragma unroll
            for (int t = 0; t < 8; t++) {
                #pragma unroll
                for (int r = 0; r < FC_ROWS; r++) {
                    u64 nv = *(const u64*)&sN[r*64 + 2*(kb+t)];
                    acc[r] = fma2(wp[t], nv, acc[r]);
                }
            }
        }
        float bb = fc1b[c];
        #pragma unroll
        for (int r = 0; r < FC_ROWS; r++) {
            float2 s = upk2(acc[r]);
            sF1[r*256 + c] = fmaxf(s.x + s.y + bb, 0.f);
        }
    }
    __syncthreads();

    // fc2: 256 -> 256, 16-pair (32 LDG) batches
    {
        const int c = tid;
        u64 acc[FC_ROWS];
        #pragma unroll
        for (int r = 0; r < FC_ROWS; r++) acc[r] = 0ULL;
        #pragma unroll
        for (int kb = 0; kb < 128; kb += 16) {
            u64 wp[16];
            #pragma unroll
            for (int t = 0; t < 16; t++)
                wp[t] = pk2(fc2w[(2*(kb+t))*256 + c], fc2w[(2*(kb+t)+1)*256 + c]);
            #pragma unroll
            for (int t = 0; t < 16; t++) {
                #pragma unroll
                for (int r = 0; r < FC_ROWS; r++) {
                    u64 fv = *(const u64*)&sF1[r*256 + 2*(kb+t)];
                    acc[r] = fma2(wp[t], fv, acc[r]);
                }
            }
        }
        float bb = fc2b[c];
        #pragma unroll
        for (int r = 0; r < FC_ROWS; r++) {
            float2 s = upk2(acc[r]);
            sF2[r*256 + c] = fmaxf(s.x + s.y + bb, 0.f);
        }
    }
    __syncthreads();

    // fc3: 256 -> 2, tanh.  12 tasks (r,o) on warps 0-2, 8-lane groups.
    const int warp = tid >> 5, lane = tid & 31;
    const int grp = lane >> 3, q = lane & 7;
    const int task = warp * 4 + grp;
    if (task < FC_ROWS * 2) {
        const int r = task >> 1, o = task & 1;
        float acc = 0.f;
        #pragma unroll
        for (int m = 0; m < 8; m++) {
            int k = m*32 + q*4;
            float4 f = *(const float4*)&sF2[r*256 + k];
            acc = fmaf(f.x, fc3w[(k+0)*2 + o], acc);
            acc = fmaf(f.y, fc3w[(k+1)*2 + o], acc);
            acc = fmaf(f.z, fc3w[(k+2)*2 + o], acc);
            acc = fmaf(f.w, fc3w[(k+3)*2 + o], acc);
        }
        acc += __shfl_xor_sync(0xffffffffu, acc, 1);
        acc += __shfl_xor_sync(0xffffffffu, acc, 2);
        acc += __shfl_xor_sync(0xffffffffu, acc, 4);
        if (q == 0 && r0 + r < B)
            out[(r0 + r)*2 + o] = tanhf(acc + fc3b[o]);
    }
}

extern "C" void kernel_launch(void* const* d_in, const int* in_sizes, int n_in,
                              void* d_out, int out_size) {
    const float* state24 = (const float*)d_in[0];
    const float* Wl1  = (const float*)d_in[1];
    const float* Wr1  = (const float*)d_in[2];
    const float* att1 = (const float*)d_in[3];
    const float* b1   = (const float*)d_in[4];
    const float* Wl2  = (const float*)d_in[5];
    const float* Wr2  = (const float*)d_in[6];
    const float* att2 = (const float*)d_in[7];
    const float* b2   = (const float*)d_in[8];
    const float* fc1w = (const float*)d_in[9];
    const float* fc1b = (const float*)d_in[10];
    const float* fc2w = (const float*)d_in[11];
    const float* fc2b = (const float*)d_in[12];
    const float* fc3w = (const float*)d_in[13];
    const float* fc3b = (const float*)d_in[14];
    float* out = (float*)d_out;

    const int B = in_sizes[0] / 24;
    const size_t smem = SMEM_FLOATS * sizeof(float);   // 37,632 B
    cudaFuncSetAttribute(actor_kernel, cudaFuncAttributeMaxDynamicSharedMemorySize, (int)smem);

    actor_kernel<<<B, NTHREADS, smem>>>(state24, Wl1, Wr1, att1, b1,
                                        Wl2, Wr2, att2, b2);
    fc_kernel<<<(B + FC_ROWS - 1) / FC_ROWS, 256>>>(fc1w, fc1b, fc2w, fc2b,
                                                    fc3w, fc3b, out, B);
}

// round 15
// speedup vs baseline: 1.0305x; 1.0305x over previous
#include <cuda_runtime.h>
#include <math.h>

#define NTHREADS 256
#define MAXB 8192

__device__ float g_nfv[MAXB * 64];

typedef unsigned long long u64;

// ---- f32x2 packed helpers (sm_100+) ----
__device__ __forceinline__ u64 pk2(float a, float b) {
    u64 r; asm("mov.b64 %0, {%1,%2};" : "=l"(r) : "f"(a), "f"(b)); return r;
}
__device__ __forceinline__ float2 upk2(u64 v) {
    float2 r; asm("mov.b64 {%0,%1}, %2;" : "=f"(r.x), "=f"(r.y) : "l"(v)); return r;
}
__device__ __forceinline__ u64 fma2(u64 a, u64 b, u64 c) {
    u64 d; asm("fma.rn.f32x2 %0, %1, %2, %3;" : "=l"(d) : "l"(a), "l"(b), "l"(c)); return d;
}
__device__ __forceinline__ u64 mul2(u64 a, u64 b) {
    u64 d; asm("mul.rn.f32x2 %0, %1, %2;" : "=l"(d) : "l"(a), "l"(b)); return d;
}
__device__ __forceinline__ u64 add2(u64 a, u64 b) {
    u64 d; asm("add.rn.f32x2 %0, %1, %2;" : "=l"(d) : "l"(a), "l"(b)); return d;
}
__device__ __forceinline__ u64 abs2(u64 a) {
    u64 d; asm("and.b64 %0, %1, %2;" : "=l"(d) : "l"(a), "l"(0x7FFFFFFF7FFFFFFFULL)); return d;
}

__device__ __forceinline__ float red8(float p) {
    p += __shfl_xor_sync(0xffffffffu, p, 1);
    p += __shfl_xor_sync(0xffffffffu, p, 2);
    p += __shfl_xor_sync(0xffffffffu, p, 4);
    return p;
}
__device__ __forceinline__ float hsum(u64 t) { float2 v = upk2(t); return v.x + v.y; }

__device__ __forceinline__ float dot8p(ulonglong2 A0, ulonglong2 A1,
                                       u64 r0, u64 r1, u64 r2, u64 r3) {
    u64 t = mul2(A0.x, r0);
    t = fma2(A0.y, r1, t);
    t = fma2(A1.x, r2, t);
    t = fma2(A1.y, r3, t);
    return hsum(t);
}
__device__ __forceinline__ float absdot8p(ulonglong2 A0, ulonglong2 A1,
                                          ulonglong2 G0, ulonglong2 G1,
                                          u64 r0, u64 r1, u64 r2, u64 r3) {
    u64 t = mul2(A0.x, abs2(add2(G0.x, r0)));
    t = fma2(A0.y, abs2(add2(G0.y, r1)), t);
    t = fma2(A1.x, abs2(add2(G1.x, r2)), t);
    t = fma2(A1.y, abs2(add2(G1.y, r3)), t);
    return hsum(t);
}

// smem layout (floats) — 9408 floats = 37,632 B; smem/SM=188KB @occ5 -> L1D=40KB
#define OFF_ATT1 0      // 256
#define OFF_B1   256    // 256
#define OFF_ATT2 512    // 64
#define OFF_B2   576    // 64
#define OFF_X    640    // 168
#define OFF_AJ   808    // 88   (A2 / colsum reuse this after layer 1)
#define OFF_GL1  896    // 5376 (21x256) -> h1 after step E
#define OFF_SCR  6272   // 3136 scratch
#define SMEM_FLOATS 9408
// scratch life: e1 [i*84+j*4+h] (1764) -> alphaT [h*504+j*24+i] (2016, after D barrier)
//            -> gl2 @0 (1344), gr2 @1344 (1344), e2 @2688 (441).

__global__ __launch_bounds__(NTHREADS, 5) void actor_kernel(
    const float* __restrict__ state24,
    const float* __restrict__ Wl1, const float* __restrict__ Wr1,
    const float* __restrict__ att1, const float* __restrict__ b1,
    const float* __restrict__ Wl2, const float* __restrict__ Wr2,
    const float* __restrict__ att2, const float* __restrict__ b2)
{
    extern __shared__ float sm[];
    float* sAtt1 = sm + OFF_ATT1;
    float* sB1   = sm + OFF_B1;
    float* sAtt2 = sm + OFF_ATT2;
    float* sB2   = sm + OFF_B2;
    float* sX    = sm + OFF_X;
    float* sAj   = sm + OFF_AJ;
    float* sGL1  = sm + OFF_GL1;
    float* sSCR  = sm + OFF_SCR;

    const int tid  = threadIdx.x;
    const int lane = tid & 31;
    const int warp = tid >> 5;
    const int b    = blockIdx.x;
    const float* st = state24 + b * 24;

    const int g = lane >> 3, q = lane & 7;
    const int off0 = g * 64 + q * 4;
    const int off1 = off0 + 32;
    const int offq0 = q * 4;
    const int offq1 = q * 4 + 32;

    sAtt1[tid] = att1[tid];
    sB1[tid]   = b1[tid];
    if (tid < 64) { sAtt2[tid] = att2[tid]; sB2[tid] = b2[tid]; }

    if (tid < 21) {
        float f0, f1, f2, f3, f4, f5, f6;
        if (tid < 20) {
            double ang = (-1.6007963267948966 + 0.15707963267948966)
                       + (double)tid * 0.15857963267948968;
            float a = (float)ang;
            f0 = st[tid] * 0.1f;
            f1 = sinf(a); f2 = cosf(a);
            f3 = f4 = f5 = f6 = 0.f;
        } else {
            f0 = f1 = f2 = 0.f;
            f3 = st[20]; f4 = st[21]; f5 = st[22]; f6 = st[23];
        }
        float* xr = sX + tid * 8;
        xr[0]=f0; xr[1]=f1; xr[2]=f2; xr[3]=f3; xr[4]=f4; xr[5]=f5; xr[6]=f6; xr[7]=0.f;
    }
    __syncthreads();

    // ---- B: gl1 = x @ Wl1 ----
    {
        const int c = tid;
        float wl[7];
        #pragma unroll
        for (int k = 0; k < 7; k++) wl[k] = Wl1[k*256 + c];
        #pragma unroll 3
        for (int i = 0; i < 21; i++) {
            const float* xr = sX + i*8;
            float a = 0.f;
            #pragma unroll
            for (int k = 0; k < 7; k++) a = fmaf(xr[k], wl[k], a);
            sGL1[i*256 + c] = a;
        }
    }
    __syncthreads();

    const ulonglong2 A0 = *(const ulonglong2*)&sAtt1[off0];
    const ulonglong2 A1 = *(const ulonglong2*)&sAtt1[off1];

    // ---- Aj ----
    for (int j = warp; j < 21; j += 8) {
        ulonglong2 G0 = *(const ulonglong2*)&sGL1[j*256 + off0];
        ulonglong2 G1 = *(const ulonglong2*)&sGL1[j*256 + off1];
        float p = red8(dot8p(A0, A1, G0.x, G0.y, G1.x, G1.y));
        if (q == 0) sAj[j*4 + g] = p;
    }
    __syncthreads();

    // ---- C: e1[i,j,h] = 0.6(A_j + B_i) + 0.4 * sum_d att|gl_j + gr_i| ----
    {
        float* sE1 = sSCR;
        {
            const int i0 = warp, i1 = warp + 8;
            u64 ra[4] = {0,0,0,0}, rb[4] = {0,0,0,0};
            #pragma unroll
            for (int m = 0; m < 7; m++) {
                ulonglong2 w0 = *(const ulonglong2*)&Wr1[m*256 + off0];
                ulonglong2 w1 = *(const ulonglong2*)&Wr1[m*256 + off1];
                float xav = sX[i0*8 + m], xbv = sX[i1*8 + m];
                u64 xa = pk2(xav, xav), xb = pk2(xbv, xbv);
                ra[0] = fma2(xa, w0.x, ra[0]); ra[1] = fma2(xa, w0.y, ra[1]);
                ra[2] = fma2(xa, w1.x, ra[2]); ra[3] = fma2(xa, w1.y, ra[3]);
                rb[0] = fma2(xb, w0.x, rb[0]); rb[1] = fma2(xb, w0.y, rb[1]);
                rb[2] = fma2(xb, w1.x, rb[2]); rb[3] = fma2(xb, w1.y, rb[3]);
            }
            float Bp0 = red8(dot8p(A0, A1, ra[0], ra[1], ra[2], ra[3]));
            float Bp1 = red8(dot8p(A0, A1, rb[0], rb[1], rb[2], rb[3]));
            #pragma unroll 3
            for (int j = 0; j < 21; j++) {
                ulonglong2 G0 = *(const ulonglong2*)&sGL1[j*256 + off0];
                ulonglong2 G1 = *(const ulonglong2*)&sGL1[j*256 + off1];
                float t0 = absdot8p(A0, A1, G0, G1, ra[0], ra[1], ra[2], ra[3]);
                float t1 = absdot8p(A0, A1, G0, G1, rb[0], rb[1], rb[2], rb[3]);
                t0 = red8(t0);
                t1 = red8(t1);
                if (q == 0) {
                    float ajv = sAj[j*4 + g];
                    sE1[(i0*21 + j)*4 + g] = fmaf(0.4f, t0, 0.6f * (ajv + Bp0));
                    sE1[(i1*21 + j)*4 + g] = fmaf(0.4f, t1, 0.6f * (ajv + Bp1));
                }
            }
        }
        if (warp < 5) {
            const int i2 = warp + 16;
            u64 rr[4] = {0,0,0,0};
            #pragma unroll
            for (int m = 0; m < 7; m++) {
                ulonglong2 w0 = *(const ulonglong2*)&Wr1[m*256 + off0];
                ulonglong2 w1 = *(const ulonglong2*)&Wr1[m*256 + off1];
                float xv = sX[i2*8 + m];
                u64 xp = pk2(xv, xv);
                rr[0] = fma2(xp, w0.x, rr[0]); rr[1] = fma2(xp, w0.y, rr[1]);
                rr[2] = fma2(xp, w1.x, rr[2]); rr[3] = fma2(xp, w1.y, rr[3]);
            }
            float Bp = red8(dot8p(A0, A1, rr[0], rr[1], rr[2], rr[3]));
            #pragma unroll 3
            for (int j = 0; j < 21; j++) {
                ulonglong2 G0 = *(const ulonglong2*)&sGL1[j*256 + off0];
                ulonglong2 G1 = *(const ulonglong2*)&sGL1[j*256 + off1];
                float t = red8(absdot8p(A0, A1, G0, G1, rr[0], rr[1], rr[2], rr[3]));
                if (q == 0)
                    sE1[(i2*21 + j)*4 + g] = fmaf(0.4f, t, 0.6f * (sAj[j*4 + g] + Bp));
            }
        }
    }
    __syncthreads();

    // ---- D: softmax over j (e1 -> regs), barrier, write alphaT over e1 ----
    {
        float v[21];
        const int i = tid >> 2, h = tid & 3;
        if (tid < 84) {
            const float* row = sSCR + i*84 + h;
            float m = -1e30f;
            #pragma unroll
            for (int j = 0; j < 21; j++) { v[j] = row[j*4]; m = fmaxf(m, v[j]); }
            float s = 0.f;
            #pragma unroll
            for (int j = 0; j < 21; j++) { v[j] = __expf(v[j] - m); s += v[j]; }
            float inv = 1.f / s;
            #pragma unroll
            for (int j = 0; j < 21; j++) v[j] *= inv;
        }
        __syncthreads();
        if (tid < 84) {
            float* at = sSCR + h*504 + i;
            #pragma unroll
            for (int j = 0; j < 21; j++) at[j*24] = v[j];
        }
    }
    __syncthreads();

    // ---- E: h1 = elu(alpha1 @ gl1 + b1) -> overwrite sGL1 ----
    {
        const int c = tid, h = c >> 6;
        u64 acc[10];
        #pragma unroll
        for (int p = 0; p < 10; p++) acc[p] = 0ULL;
        float acc20 = 0.f;
        const float* aT = sSCR + h*504;
        #pragma unroll 3
        for (int j = 0; j < 21; j++) {
            float gv = sGL1[j*256 + c];
            u64 gg = pk2(gv, gv);
            const ulonglong2* ap = (const ulonglong2*)(aT + j*24);
            ulonglong2 p0 = ap[0];
            acc[0] = fma2(p0.x, gg, acc[0]); acc[1] = fma2(p0.y, gg, acc[1]);
            ulonglong2 p1 = ap[1];
            acc[2] = fma2(p1.x, gg, acc[2]); acc[3] = fma2(p1.y, gg, acc[3]);
            ulonglong2 p2 = ap[2];
            acc[4] = fma2(p2.x, gg, acc[4]); acc[5] = fma2(p2.y, gg, acc[5]);
            ulonglong2 p3 = ap[3];
            acc[6] = fma2(p3.x, gg, acc[6]); acc[7] = fma2(p3.y, gg, acc[7]);
            ulonglong2 p4 = ap[4];
            acc[8] = fma2(p4.x, gg, acc[8]); acc[9] = fma2(p4.y, gg, acc[9]);
            acc20 = fmaf(aT[j*24 + 20], gv, acc20);
        }
        float bc = sB1[c];
        #pragma unroll
        for (int p = 0; p < 10; p++) {
            float2 v = upk2(acc[p]);
            float v0 = v.x + bc;
            float v1 = v.y + bc;
            v0 = fmaxf(v0, 0.f) + __expf(fminf(v0, 0.f)) - 1.f;
            v1 = fmaxf(v1, 0.f) + __expf(fminf(v1, 0.f)) - 1.f;
            sGL1[(2*p  )*256 + c] = v0;
            sGL1[(2*p+1)*256 + c] = v1;
        }
        float v20 = acc20 + bc;
        v20 = fmaxf(v20, 0.f) + __expf(fminf(v20, 0.f)) - 1.f;
        sGL1[20*256 + c] = v20;
    }
    __syncthreads();

    // ---- F: gl2 / gr2 = h1 @ Wl2 / Wr2 ----
    {
        const int d    = tid & 63;
        const int sel  = (tid >> 6) & 1;
        const int half = tid >> 7;
        const float* __restrict__ W = sel ? Wr2 : Wl2;
        float* G = sSCR + (sel ? 1344 : 0);
        const int i0 = half ? 11 : 0;
        u64 acc[11];
        #pragma unroll
        for (int i = 0; i < 11; i++) acc[i] = 0ULL;
        for (int k = 0; k < 256; k += 4) {
            float w0 = W[(k+0)*64 + d];
            float w1 = W[(k+1)*64 + d];
            float w2 = W[(k+2)*64 + d];
            float w3 = W[(k+3)*64 + d];
            u64 wp01 = pk2(w0, w1);
            u64 wp23 = pk2(w2, w3);
            #pragma unroll
            for (int i = 0; i < 11; i++) {
                if (i0 + i < 21) {
                    ulonglong2 h2 = *(const ulonglong2*)&sGL1[(i0+i)*256 + k];
                    acc[i] = fma2(wp01, h2.x, acc[i]);
                    acc[i] = fma2(wp23, h2.y, acc[i]);
                }
            }
        }
        #pragma unroll
        for (int i = 0; i < 11; i++) {
            if (i0 + i < 21) {
                float2 s = upk2(acc[i]);
                G[(i0+i)*64 + d] = s.x + s.y;
            }
        }
    }
    __syncthreads();

    const ulonglong2 A0q = *(const ulonglong2*)&sAtt2[offq0];
    const ulonglong2 A1q = *(const ulonglong2*)&sAtt2[offq1];

    // ---- A2 (stored in the dead Aj slot) ----
    {
        const float* gl2 = sSCR;
        float* sA2 = sAj;
        int j = warp + 8*g;
        int jc = (j < 21) ? j : 20;
        ulonglong2 G0 = *(const ulonglong2*)&gl2[jc*64 + offq0];
        ulonglong2 G1 = *(const ulonglong2*)&gl2[jc*64 + offq1];
        float p = red8(dot8p(A0q, A1q, G0.x, G0.y, G1.x, G1.y));
        if (q == 0 && j < 21) sA2[j] = p;
    }
    __syncthreads();

    // ---- C2 ----
    {
        const float* gl2 = sSCR;
        const float* gr2 = sSCR + 1344;
        const float* sA2 = sAj;
        float* sE2 = sSCR + 2688;
        for (int i = warp; i < 21; i += 8) {
            ulonglong2 R0 = *(const ulonglong2*)&gr2[i*64 + offq0];
            ulonglong2 R1 = *(const ulonglong2*)&gr2[i*64 + offq1];
            float Bp = red8(dot8p(A0q, A1q, R0.x, R0.y, R1.x, R1.y));
            #pragma unroll
            for (int jb = 0; jb < 21; jb += 4) {
                int j = jb + g;
                int jc = (j < 21) ? j : 20;
                ulonglong2 G0 = *(const ulonglong2*)&gl2[jc*64 + offq0];
                ulonglong2 G1 = *(const ulonglong2*)&gl2[jc*64 + offq1];
                float t = red8(absdot8p(A0q, A1q, G0, G1, R0.x, R0.y, R1.x, R1.y));
                if (q == 0 && j < 21)
                    sE2[i*21 + j] = fmaf(0.4f, t, 0.6f * (sA2[j] + Bp));
            }
        }
    }
    __syncthreads();

    // ---- softmax2: 8-lane group per row; ALL lanes run ALL shfls (clamped idx) ----
    {
        float* sE2 = sSCR + 2688;
        const int i  = warp*4 + g;
        const int ic = (i < 21) ? i : 20;
        float* row = sE2 + ic*21;
        float v0 = row[q];
        float v1 = row[q + 8];
        float v2 = (q < 5) ? row[q + 16] : -1e30f;
        float m = fmaxf(fmaxf(v0, v1), v2);
        m = fmaxf(m, __shfl_xor_sync(0xffffffffu, m, 1));
        m = fmaxf(m, __shfl_xor_sync(0xffffffffu, m, 2));
        m = fmaxf(m, __shfl_xor_sync(0xffffffffu, m, 4));
        v0 = __expf(v0 - m);
        v1 = __expf(v1 - m);
        v2 = (q < 5) ? __expf(v2 - m) : 0.f;
        float s = v0 + v1 + v2;
        s += __shfl_xor_sync(0xffffffffu, s, 1);
        s += __shfl_xor_sync(0xffffffffu, s, 2);
        s += __shfl_xor_sync(0xffffffffu, s, 4);
        float inv = 1.f / s;
        if (i < 21) {
            row[q]     = v0 * inv;
            row[q + 8] = v1 * inv;
            if (q < 5) row[q + 16] = v2 * inv;
        }
    }
    __syncthreads();

    // ---- colsum: w[j] = (1/21) sum_i alpha2[i,j]  (E2+pool collapsed) ----
    if (tid < 21) {
        const float* al = sSCR + 2688;
        float s = 0.f;
        #pragma unroll 7
        for (int i = 0; i < 21; i++) s += al[i*21 + tid];
        sAj[tid] = s * (1.0f / 21.0f);     // overwrite dead A2
    }
    __syncthreads();

    // ---- nfv[d] = sum_j w[j] * gl2[j,d] + b2[d] -> global ----
    if (tid < 64) {
        const float* gl2 = sSCR;
        float acc = 0.f;
        #pragma unroll 7
        for (int j = 0; j < 21; j++) acc = fmaf(sAj[j], gl2[j*64 + tid], acc);
        g_nfv[b*64 + tid] = acc + sB2[tid];
    }
}

// ====== FC head kernel: 8 rows/block (best measured config), deep LDG batching ======
#define FC_ROWS 8

__global__ __launch_bounds__(256, 2) void fc_kernel(
    const float* __restrict__ fc1w, const float* __restrict__ fc1b,
    const float* __restrict__ fc2w, const float* __restrict__ fc2b,
    const float* __restrict__ fc3w, const float* __restrict__ fc3b,
    float* __restrict__ out, int B)
{
    __shared__ float sN [FC_ROWS * 64];
    __shared__ float sF1[FC_ROWS * 256];
    __shared__ float sF2[FC_ROWS * 256];
    const int tid = threadIdx.x;
    const int r0  = blockIdx.x * FC_ROWS;

    if (tid < 128)
        ((float4*)sN)[tid] = *(const float4*)&g_nfv[r0*64 + tid*4];
    __syncthreads();

    // fc1: 64 -> 256, 8-pair (16 LDG) batches
    {
        const int c = tid;
        u64 acc[FC_ROWS];
        #pragma unroll
        for (int r = 0; r < FC_ROWS; r++) acc[r] = 0ULL;
        #pragma unroll
        for (int kb = 0; kb < 32; kb += 8) {
            u64 wp[8];
            #pragma unroll
            for (int t = 0; t < 8; t++)
                wp[t] = pk2(fc1w[(2*(kb+t))*256 + c], fc1w[(2*(kb+t)+1)*256 + c]);
            #pragma unroll
            for (int t = 0; t < 8; t++) {
                #pragma unroll
                for (int r = 0; r < FC_ROWS; r++) {
                    u64 nv = *(const u64*)&sN[r*64 + 2*(kb+t)];
                    acc[r] = fma2(wp[t], nv, acc[r]);
                }
            }
        }
        float bb = fc1b[c];
        #pragma unroll
        for (int r = 0; r < FC_ROWS; r++) {
            float2 s = upk2(acc[r]);
            sF1[r*256 + c] = fmaxf(s.x + s.y + bb, 0.f);
        }
    }
    __syncthreads();

    // fc2: 256 -> 256, 16-pair (32 LDG) batches
    {
        const int c = tid;
        u64 acc[FC_ROWS];
        #pragma unroll
        for (int r = 0; r < FC_ROWS; r++) acc[r] = 0ULL;
        #pragma unroll
        for (int kb = 0; kb < 128; kb += 16) {
            u64 wp[16];
            #pragma unroll
            for (int t = 0; t < 16; t++)
                wp[t] = pk2(fc2w[(2*(kb+t))*256 + c], fc2w[(2*(kb+t)+1)*256 + c]);
            #pragma unroll
            for (int t = 0; t < 16; t++) {
                #pragma unroll
                for (int r = 0; r < FC_ROWS; r++) {
                    u64 fv = *(const u64*)&sF1[r*256 + 2*(kb+t)];
                    acc[r] = fma2(wp[t], fv, acc[r]);
                }
            }
        }
        float bb = fc2b[c];
        #pragma unroll
        for (int r = 0; r < FC_ROWS; r++) {
            float2 s = upk2(acc[r]);
            sF2[r*256 + c] = fmaxf(s.x + s.y + bb, 0.f);
        }
    }
    __syncthreads();

    // fc3: 256 -> 2, tanh.  16 tasks (r,o) on warps 0-3, 8-lane groups.
    const int warp = tid >> 5, lane = tid & 31;
    const int grp = lane >> 3, q = lane & 7;
    const int task = warp * 4 + grp;
    if (task < 16) {
        const int r = task >> 1, o = task & 1;
        float acc = 0.f;
        #pragma unroll
        for (int m = 0; m < 8; m++) {
            int k = m*32 + q*4;
            float4 f = *(const float4*)&sF2[r*256 + k];
            acc = fmaf(f.x, fc3w[(k+0)*2 + o], acc);
            acc = fmaf(f.y, fc3w[(k+1)*2 + o], acc);
            acc = fmaf(f.z, fc3w[(k+2)*2 + o], acc);
            acc = fmaf(f.w, fc3w[(k+3)*2 + o], acc);
        }
        acc += __shfl_xor_sync(0xffffffffu, acc, 1);
        acc += __shfl_xor_sync(0xffffffffu, acc, 2);
        acc += __shfl_xor_sync(0xffffffffu, acc, 4);
        if (q == 0 && r0 + r < B)
            out[(r0 + r)*2 + o] = tanhf(acc + fc3b[o]);
    }
}

extern "C" void kernel_launch(void* const* d_in, const int* in_sizes, int n_in,
                              void* d_out, int out_size) {
    const float* state24 = (const float*)d_in[0];
    const float* Wl1  = (const float*)d_in[1];
    const float* Wr1  = (const float*)d_in[2];
    const float* att1 = (const float*)d_in[3];
    const float* b1   = (const float*)d_in[4];
    const float* Wl2  = (const float*)d_in[5];
    const float* Wr2  = (const float*)d_in[6];
    const float* att2 = (const float*)d_in[7];
    const float* b2   = (const float*)d_in[8];
    const float* fc1w = (const float*)d_in[9];
    const float* fc1b = (const float*)d_in[10];
    const float* fc2w = (const float*)d_in[11];
    const float* fc2b = (const float*)d_in[12];
    const float* fc3w = (const float*)d_in[13];
    const float* fc3b = (const float*)d_in[14];
    float* out = (float*)d_out;

    const int B = in_sizes[0] / 24;
    const size_t smem = SMEM_FLOATS * sizeof(float);   // 37,632 B
    cudaFuncSetAttribute(actor_kernel, cudaFuncAttributeMaxDynamicSharedMemorySize, (int)smem);

    actor_kernel<<<B, NTHREADS, smem>>>(state24, Wl1, Wr1, att1, b1,
                                        Wl2, Wr2, att2, b2);
    fc_kernel<<<(B + FC_ROWS - 1) / FC_ROWS, 256>>>(fc1w, fc1b, fc2w, fc2b,
                                                    fc3w, fc3b, out, B);
}